// round 14
// baseline (speedup 1.0000x reference)
#include <cuda_runtime.h>
#include <cuda_bf16.h>
#include <cstdint>

// Levinson-Durbin, M=24. ONE row per thread; 4 autonomous warps per CTA,
// each owning a private 32-row tile moved by cp.async.bulk (one instruction
// per direction instead of per-thread copy loops).
// out[row] = [K, a0..a23],  R a = -r1,  K = sqrt(E_24).
//
// R13 design (kernel is TOTAL-ISSUE bound: 1140 instrs/warp, only 605 FMAs):
//  - cp.async.bulk gmem->smem with mbarrier completion: warp tile is a flat
//    3200B 16B-aligned block -> 1 bulk copy replaces 7 cp.async/thread.
//  - cp.async.bulk smem->gmem (bulk_group) for the output: replaces the
//    7x(LDS.128+STG.128)/thread drain loop.
//  - TPB=128 / grid=2048: quarters CTA-dispatch & ramp overhead vs TPB=32.
//  - math unchanged from R11: serial dot m<=11, 2-way m>=12, pipelined
//    rcp(-E), E += k*acc, sqrt.approx.

constexpr int M_ORD = 24;
constexpr int NC    = M_ORD + 1;               // 25
constexpr int TPB   = 128;
constexpr int WARPS = TPB / 32;                // 4
constexpr int ROWS_PER_WARP = 32;
constexpr int RPB   = WARPS * ROWS_PER_WARP;   // 128 rows per CTA
constexpr int WTILE_FLOATS = ROWS_PER_WARP * NC;   // 800
constexpr int WTILE_BYTES  = WTILE_FLOATS * 4;     // 3200 (16B multiple)

// -(1/x): negation folded into the MUFU operand
__device__ __forceinline__ float nrcp(float x) {
    float y; asm("rcp.approx.f32 %0, %1;" : "=f"(y) : "f"(-x)); return y;
}
__device__ __forceinline__ float fsqrt_fast(float x) {
    float y; asm("sqrt.approx.f32 %0, %1;" : "=f"(y) : "f"(x)); return y;
}
__device__ __forceinline__ unsigned smem_u32(const void* p) {
    return (unsigned)__cvta_generic_to_shared(p);
}

// Full Levinson-Durbin recursion; returns K = sqrt(E_M), fills a[0..23].
__device__ __forceinline__ float levdur(const float rr[NC], float a[M_ORD]) {
    float E     = rr[0];
    float ninvE = nrcp(E);                     // -1/E, pipelined one iter ahead
    #pragma unroll
    for (int m = 0; m < M_ORD; m++) {
        float acc;
        if (m <= 11) {
            float s0 = rr[m + 1];
            #pragma unroll
            for (int i = 0; i < m; i++) s0 = fmaf(a[i], rr[m - i], s0);
            acc = s0;
        } else {
            float s0 = rr[m + 1], s1 = 0.0f;
            #pragma unroll
            for (int i = 0; i + 1 < m; i += 2) {
                s0 = fmaf(a[i    ], rr[m - i    ], s0);
                s1 = fmaf(a[i + 1], rr[m - i - 1], s1);
            }
            if (m & 1) s0 = fmaf(a[m - 1], rr[1], s0);
            acc = s0 + s1;
        }

        float k = acc * ninvE;                 // k = -acc/E (MUFU hidden)

        // symmetric in-place update: a_i' = a_i + k * a_{m-1-i}
        #pragma unroll
        for (int i = 0; i < m / 2; i++) {
            float t = a[i];
            float u = a[m - 1 - i];
            a[i]         = fmaf(k, u, t);
            a[m - 1 - i] = fmaf(k, t, u);
        }
        if (m & 1) {
            float t = a[m / 2];
            a[m / 2] = fmaf(k, t, t);
        }
        a[m] = k;

        E     = fmaf(k, acc, E);               // E *= (1 - k^2)
        ninvE = nrcp(E);                       // hides under next dot
    }
    return fsqrt_fast(E);
}

__global__ __launch_bounds__(TPB)
void levinson_durbin_kernel(const float* __restrict__ r,
                            float* __restrict__ out,
                            int nrows)
{
    __shared__ float sbuf[WARPS][WTILE_FLOATS];          // 12.8 KB
    __shared__ alignas(8) unsigned long long mbar[WARPS];
    const int lane  = threadIdx.x & 31;
    const int wid   = threadIdx.x >> 5;
    const int wrow0 = blockIdx.x * RPB + wid * ROWS_PER_WARP;

    float rr[NC];
    float a[M_ORD];

    if (wrow0 + ROWS_PER_WARP <= nrows) {
        const unsigned sb = smem_u32(&sbuf[wid][0]);
        const unsigned mb = smem_u32(&mbar[wid]);

        // ---- one-shot bulk async load of this warp's 3200B tile ----
        if (lane == 0) {
            asm volatile("mbarrier.init.shared.b64 [%0], 1;" :: "r"(mb) : "memory");
            asm volatile("fence.proxy.async.shared::cta;" ::: "memory");
            asm volatile("mbarrier.arrive.expect_tx.shared.b64 _, [%0], %1;"
                         :: "r"(mb), "r"(WTILE_BYTES) : "memory");
            asm volatile(
                "cp.async.bulk.shared::cta.global.mbarrier::complete_tx::bytes "
                "[%0], [%1], %2, [%3];"
                :: "r"(sb), "l"(r + (size_t)wrow0 * NC), "r"(WTILE_BYTES), "r"(mb)
                : "memory");
        }
        // all lanes wait on the warp-private barrier (phase 0)
        {
            unsigned done;
            asm volatile(
                "{\n\t.reg .pred p;\n\t"
                "mbarrier.try_wait.parity.acquire.cta.shared::cta.b64 p, [%1], 0;\n\t"
                "selp.b32 %0, 1, 0, p;\n\t}"
                : "=r"(done) : "r"(mb) : "memory");
            if (!done) {
                asm volatile(
                    "{\n\t.reg .pred P1;\n\t"
                    "W%=:\n\t"
                    "mbarrier.try_wait.parity.acquire.cta.shared::cta.b64 P1, [%0], 0, 0x989680;\n\t"
                    "@P1 bra.uni D%=;\n\t"
                    "bra.uni W%=;\n\t"
                    "D%=:\n\t}"
                    :: "r"(mb) : "memory");
            }
        }
        __syncwarp();

        // stride-25 (odd) per-thread reads: bank-conflict-free
        #pragma unroll
        for (int i = 0; i < NC; i++) rr[i] = sbuf[wid][lane * NC + i];

        float Kv = levdur(rr, a);

        // stage output into own row (owner-only writes)
        sbuf[wid][lane * NC + 0] = Kv;
        #pragma unroll
        for (int i = 0; i < M_ORD; i++) sbuf[wid][lane * NC + 1 + i] = a[i];
        __syncwarp();

        // ---- one-shot bulk async store of the 3200B result tile ----
        if (lane == 0) {
            asm volatile("fence.proxy.async.shared::cta;" ::: "memory");
            asm volatile(
                "cp.async.bulk.global.shared::cta.bulk_group [%0], [%1], %2;"
                :: "l"(out + (size_t)wrow0 * NC), "r"(sb), "r"(WTILE_BYTES)
                : "memory");
            asm volatile("cp.async.bulk.commit_group;" ::: "memory");
            asm volatile("cp.async.bulk.wait_group 0;" ::: "memory");
        }
    } else {
        // generic tail path (not hit for BATCH=262144)
        int row = wrow0 + lane;
        if (row < nrows) {
            #pragma unroll
            for (int i = 0; i < NC; i++) rr[i] = r[(size_t)row * NC + i];
            float Kv = levdur(rr, a);
            out[(size_t)row * NC + 0] = Kv;
            #pragma unroll
            for (int i = 0; i < M_ORD; i++)
                out[(size_t)row * NC + 1 + i] = a[i];
        }
    }
}

extern "C" void kernel_launch(void* const* d_in, const int* in_sizes, int n_in,
                              void* d_out, int out_size)
{
    const float* r = (const float*)d_in[0];
    float* out = (float*)d_out;
    const int nrows = in_sizes[0] / NC;
    const int grid = (nrows + RPB - 1) / RPB;
    levinson_durbin_kernel<<<grid, TPB>>>(r, out, nrows);
}